// round 15
// baseline (speedup 1.0000x reference)
#include <cuda_runtime.h>
#include <math.h>
#include <stdint.h>

#define BB 32
#define HH 256
#define LL 2048
#define NS 64
#define FF 32
#define BHL (BB*HH*LL)
#define TT 64
#define NCH 32

// ---------------- tf32 helpers ----------------
__device__ __forceinline__ uint32_t tf32c(float x) {
    uint32_t r; asm("cvt.rna.tf32.f32 %0, %1;" : "=r"(r) : "f"(x)); return r;
}
__device__ __forceinline__ float rtf(float x) { return __uint_as_float(tf32c(x)); }
__device__ __forceinline__ void mma8(float d[4], const uint32_t a[4], const uint32_t b[2]) {
    asm("mma.sync.aligned.m16n8k8.row.col.f32.tf32.tf32.f32 "
        "{%0,%1,%2,%3}, {%4,%5,%6,%7}, {%8,%9}, {%0,%1,%2,%3};"
        : "+f"(d[0]), "+f"(d[1]), "+f"(d[2]), "+f"(d[3])
        : "r"(a[0]), "r"(a[1]), "r"(a[2]), "r"(a[3]), "r"(b[0]), "r"(b[1]));
}

// ---------------- cp.async helpers ----------------
__device__ __forceinline__ void cpa16(uint32_t s, const float* g) {
    asm volatile("cp.async.cg.shared.global [%0], [%1], 16;" :: "r"(s), "l"(g));
}
__device__ __forceinline__ void cp_commit() { asm volatile("cp.async.commit_group;"); }
__device__ __forceinline__ void cp_wait1()  { asm volatile("cp.async.wait_group 1;"); }
__device__ __forceinline__ void cp_wait0()  { asm volatile("cp.async.wait_group 0;"); }

__device__ __forceinline__ float gatef(float o) {
    float u = __expf(fminf(-o, 25.f));
    float u2 = u * u;
    return (1.f - u2) / ((1.f + u2) * (1.f + u));
}
__device__ __forceinline__ float geluf(float y) {
    float u = 0.7978845608028654f * fmaf(0.044715f*y, y*y, y);
    float e = __expf(fminf(-2.f*u, 80.f));
    float th = (1.f - e) / (1.f + e);
    return 0.5f*y*(1.f + th);
}

// ---------------- scratch ----------------
__device__ float g_tb[BB*HH];
__device__ float g_z [BHL];
__device__ float g_yf[BHL];   // fwd scan out; after ticket: tf32(gelu(yf+yb))
__device__ float g_yb[BHL];   // bwd scan out (+ D*z folded)
__device__ int   g_cnt[BB*HH];
// tf32-pre-rounded GEMM operands
__device__ float g_WoutT[HH*HH], g_W1T[HH*HH], g_W2T[HH*HH], g_WfT[HH*FF];
__device__ float g_ft[BB*FF*LL];
// chunked-scan matrices per (h,dir)
__device__ float g_G[2*HH][64*192];   // [Ktoeplitz | CO_re | -CO_im]
__device__ float g_H[2*HH][128*64];   // [WA_re ; WA_im]
__device__ float g_wTd[2*HH][128];    // w^64 re(0..63), im(64..127)

// ---------------- pre-round weights to tf32 (+ zero tickets) ----------------
__global__ void k_cvtw(const float* __restrict__ Wout, const float* __restrict__ W1,
                       const float* __restrict__ W2, const float* __restrict__ Wf)
{
    int i = blockIdx.x*256 + threadIdx.x;      // 0..65535
    g_WoutT[i] = rtf(Wout[i]);
    g_W1T[i]   = rtf(W1[i]);
    g_W2T[i]   = rtf(W2[i]);
    if (i < HH*FF) g_WfT[i] = rtf(Wf[i]);
    if (i < HH) g_cnt[i] = 0;
}

// ---------------- t @ Wt^T + bt ----------------
__global__ void k_tb(const float* __restrict__ t, const float* __restrict__ Wt,
                     const float* __restrict__ bt)
{
    __shared__ float ts[HH];
    __shared__ float part[64][4];
    int b  = blockIdx.y;
    int h0 = blockIdx.x * 64;
    int tid = threadIdx.x;
    ts[tid] = t[b*HH + tid];
    __syncthreads();
    int hl = tid >> 2, ks = tid & 3;
    int h = h0 + hl;
    const float* wrow = Wt + (size_t)h*HH + ks*64;
    const float* tsp  = ts + ks*64;
    float acc = 0.f;
    #pragma unroll 16
    for (int k = 0; k < 64; k++) acc = fmaf(tsp[k], wrow[k], acc);
    part[hl][ks] = acc;
    __syncthreads();
    if (ks == 0)
        g_tb[b*HH + h] = part[hl][0] + part[hl][1] + part[hl][2] + part[hl][3] + bt[h];
}

// ---------------- chunked-scan matrix prep: one block per (h,dir) ----------------
__global__ void k_prep(const float* __restrict__ log_dt, const float* __restrict__ logA_real,
                       const float* __restrict__ A_imag, const float* __restrict__ C_re,
                       const float* __restrict__ C_im)
{
    __shared__ float Ere[65][64], Eim[65][64];
    __shared__ float cdr[64], cdi[64], kv[64], sdr[64], sdi[64];
    int hd = blockIdx.x, h = hd >> 1, dir = hd & 1;
    int tid = threadIdx.x;
    if (tid < 64) {
        int n = tid, i = h*NS + n;
        float dt = expf(log_dt[h]);
        float Ar = -expf(logA_real[i]);
        float Ai = A_imag[i];
        float dr = dt*Ar, di = dt*Ai;
        sdr[n] = dr; sdi[n] = di;
        float er = expf(dr);
        float wr = er*cosf(di), wi = er*sinf(di);
        float Er = wr - 1.f, Ei = wi;
        float inv = 1.f/(Ar*Ar + Ai*Ai);
        float qr = (Er*Ar + Ei*Ai)*inv;
        float qi = (Ei*Ar - Er*Ai)*inv;
        float cr = C_re[dir*HH*NS + i], ci = C_im[dir*HH*NS + i];
        cdr[n] = 2.f*(cr*qr - ci*qi);
        cdi[n] = 2.f*(cr*qi + ci*qr);
    }
    __syncthreads();
    for (int q = tid; q < 65*64; q += 256) {
        int p = q >> 6, n = q & 63;
        float e  = expf((float)p*sdr[n]);
        float ph = (float)p*sdi[n];
        Ere[p][n] = e*cosf(ph);
        Eim[p][n] = e*sinf(ph);
    }
    __syncthreads();
    if (tid < 64) {
        int p = tid;
        float acc = 0.f;
        for (int n = 0; n < 64; n++) acc += cdr[n]*Ere[p][n] - cdi[n]*Eim[p][n];
        kv[p] = acc;
    }
    __syncthreads();
    float* Gp = g_G[hd];
    for (int q = tid; q < 64*192; q += 256) {
        int i = q / 192, col = q % 192;
        float val;
        if (col < 64) {
            int j = col;
            if (!dir) val = (j <= i) ? kv[i-j] : 0.f;
            else      val = (j >  i) ? kv[j-i-1] : 0.f;   // z[l+1] carries w^0
        } else {
            int n = (col - 64) & 63;
            int p = dir ? (63 - i) : (i + 1);
            float core = cdr[n]*Ere[p][n] - cdi[n]*Eim[p][n];
            float coim = cdr[n]*Eim[p][n] + cdi[n]*Ere[p][n];
            val = (col < 128) ? core : -coim;
        }
        Gp[q] = rtf(val);
    }
    float* Hp = g_H[hd];
    for (int q = tid; q < 128*64; q += 256) {
        int r = q >> 6, j = q & 63;
        int n = r & 63;
        int p = dir ? j : (63 - j);                        // S gathers w^j
        float val = (r < 64) ? Ere[p][n] : Eim[p][n];
        Hp[q] = rtf(val);
    }
    if (tid < 64) {
        g_wTd[hd][tid]    = Ere[64][tid];
        g_wTd[hd][64+tid] = Eim[64][tid];
    }
}

// ---------------- LayerNorm over H -> z (tf32-rounded) + feat tf32 tail ----------------
__global__ void k_ln(const float* __restrict__ x, const float* __restrict__ ln_g,
                     const float* __restrict__ ln_b, const float* __restrict__ feat)
{
    __shared__ float tbs[HH], gs[HH], bs[HH];
    __shared__ float sms[4][64], smss[4][64];
    int b = blockIdx.y;
    int tid = threadIdx.x;
    tbs[tid] = g_tb[b*HH + tid];
    gs[tid]  = ln_g[tid];
    bs[tid]  = ln_b[tid];
    __syncthreads();
    int lg = tid & 63, hg = tid >> 6;
    int l = blockIdx.x*64 + lg;
    const float* xb = x + (size_t)b*HH*LL + l;
    float s = 0.f, ss = 0.f;
    #pragma unroll 8
    for (int h = hg*64; h < hg*64 + 64; h++) {
        float v = xb[(size_t)h*LL] + tbs[h];
        s += v; ss = fmaf(v, v, ss);
    }
    sms[hg][lg] = s; smss[hg][lg] = ss;
    __syncthreads();
    float st  = sms[0][lg]  + sms[1][lg]  + sms[2][lg]  + sms[3][lg];
    float sst = smss[0][lg] + smss[1][lg] + smss[2][lg] + smss[3][lg];
    float mu  = st * (1.0f/HH);
    float var = sst*(1.0f/HH) - mu*mu;
    float rstd = rsqrtf(var + 1e-5f);
    float* zb = g_z + (size_t)b*HH*LL + l;
    #pragma unroll 8
    for (int h = hg*64; h < hg*64 + 64; h++) {
        float v = xb[(size_t)h*LL] + tbs[h];
        zb[(size_t)h*LL] = rtf((v - mu)*rstd*gs[h] + bs[h]);
    }
    // tail: feat -> tf32 pre-round
    {
        int gidx = (b*32 + blockIdx.x)*256 + tid;
        const float4* fs = (const float4*)feat;
        float4* fd = (float4*)g_ft;
        #pragma unroll
        for (int q = 0; q < 2; q++) {
            float4 v = fs[gidx*2 + q];
            v.x = rtf(v.x); v.y = rtf(v.y); v.z = rtf(v.z); v.w = rtf(v.w);
            fd[gidx*2 + q] = v;
        }
    }
}

// ---------------- chunked scan: one CTA per (h,dir), tf32 mma, coalesced I/O ----------------
#define GP 196
#define HP 68
#define VP 40
#define UP 40
#define YP 68
#define CS_WORDS (64*GP + 128*HP + 192*VP + 128*UP + 32*YP)
#define CS_BYTES (CS_WORDS*4)

__global__ __launch_bounds__(256) void k_cscan(const float* __restrict__ Dv)
{
    extern __shared__ float sm[];
    float* Gs = sm;                 // 64 x GP
    float* Hs = Gs + 64*GP;         // 128 x HP
    float* V  = Hs + 128*HP;        // 192 x VP : [Z(64); S_re(64); S_im(64)] x 32b
    float* US = V  + 192*VP;        // 128 x UP
    float* Ys = US + 128*UP;        // 32 x YP : Y staged [b][i]
    __shared__ int s_tkt;

    const int hd = blockIdx.x, h = hd >> 1, dir = hd & 1;
    const int tid = threadIdx.x;
    const int w = tid >> 5, lane = tid & 31;
    const int gr = lane >> 2, tc = lane & 3;

    // load G, H into smem
    {
        const float4* gsrc = (const float4*)g_G[hd];
        for (int q = tid; q < 64*48; q += 256) {
            int row = q / 48, c4 = q % 48;
            *(float4*)&Gs[row*GP + c4*4] = gsrc[q];
        }
        const float4* hsrc = (const float4*)g_H[hd];
        for (int q = tid; q < 128*16; q += 256) {
            int row = q / 16, c4 = q % 16;
            *(float4*)&Hs[row*HP + c4*4] = hsrc[q];
        }
    }
    // zero state region of V
    for (int q = tid; q < 128*32; q += 256)
        V[(64 + (q >> 5))*VP + (q & 31)] = 0.f;

    // fp32 state registers: thread owns n = tid>>2, b = (tid&3)*8 .. +7
    const int sn = tid >> 2, sb0 = (tid & 3)*8;
    float s_re[8], s_im[8];
    #pragma unroll
    for (int k = 0; k < 8; k++) { s_re[k] = 0.f; s_im[k] = 0.f; }
    const float wtr = g_wTd[hd][sn], wti = g_wTd[hd][64 + sn];
    const float dD = dir ? Dv[h] : 0.f;

    // z chunk loading: thread (zb, jq) loads j = jq*8 .. jq*8+7 (2x float4, coalesced)
    const int zb = tid >> 3, jq = tid & 7;
    const float* zbase = g_z + ((size_t)zb*HH + h)*LL;
    float* ybase = dir ? g_yb : g_yf;

    // coalesced Y writer indices: thread covers (yb, yi..yi+7)
    const int yb = tid >> 3, yi = (tid & 7)*8;

    const int ch0 = dir ? (NCH - 1) : 0;
    const int stp = dir ? -1 : 1;
    {
        float4 z0 = *(const float4*)&zbase[ch0*TT + jq*8];
        float4 z1 = *(const float4*)&zbase[ch0*TT + jq*8 + 4];
        V[(jq*8+0)*VP + zb] = z0.x; V[(jq*8+1)*VP + zb] = z0.y;
        V[(jq*8+2)*VP + zb] = z0.z; V[(jq*8+3)*VP + zb] = z0.w;
        V[(jq*8+4)*VP + zb] = z1.x; V[(jq*8+5)*VP + zb] = z1.y;
        V[(jq*8+6)*VP + zb] = z1.z; V[(jq*8+7)*VP + zb] = z1.w;
    }
    __syncthreads();

    for (int cc = 0; cc < NCH; cc++) {
        int c = ch0 + stp*cc;
        // prefetch next chunk's z into regs (coalesced float4)
        float4 z0, z1;
        if (cc + 1 < NCH) {
            int cn = c + stp;
            z0 = *(const float4*)&zbase[cn*TT + jq*8];
            z1 = *(const float4*)&zbase[cn*TT + jq*8 + 4];
        }

        if (w < 4) {
            // Y GEMM: rows w*16..+16, K=192, N=32
            float dY[4][4];
            #pragma unroll
            for (int ni = 0; ni < 4; ni++)
                #pragma unroll
                for (int q = 0; q < 4; q++) dY[ni][q] = 0.f;
            const float* Ab = Gs + (w*16 + gr)*GP + tc;
            #pragma unroll
            for (int kk = 0; kk < 24; kk++) {
                uint32_t a[4], bb[4][2];
                const float* ap = Ab + kk*8;
                a[0] = __float_as_uint(ap[0]);
                a[1] = __float_as_uint(ap[8*GP]);
                a[2] = __float_as_uint(ap[4]);
                a[3] = __float_as_uint(ap[8*GP + 4]);
                const float* bp = V + (kk*8 + tc)*VP + gr;
                #pragma unroll
                for (int ni = 0; ni < 4; ni++) {
                    bb[ni][0] = __float_as_uint(bp[ni*8]);
                    bb[ni][1] = __float_as_uint(bp[4*VP + ni*8]);
                }
                #pragma unroll
                for (int ni = 0; ni < 4; ni++) mma8(dY[ni], a, bb[ni]);
            }
            // stage Y into smem [b][i] (+ D*z for bwd)
            int i0 = w*16 + gr;
            #pragma unroll
            for (int ni = 0; ni < 4; ni++) {
                int b0 = ni*8 + 2*tc;
                float v0 = dY[ni][0], v1 = dY[ni][1], v2 = dY[ni][2], v3 = dY[ni][3];
                if (dir) {
                    v0 = fmaf(dD, V[i0*VP + b0],       v0);
                    v1 = fmaf(dD, V[i0*VP + b0 + 1],   v1);
                    v2 = fmaf(dD, V[(i0+8)*VP + b0],   v2);
                    v3 = fmaf(dD, V[(i0+8)*VP + b0+1], v3);
                }
                Ys[b0*YP + i0]         = v0;
                Ys[(b0+1)*YP + i0]     = v1;
                Ys[b0*YP + i0 + 8]     = v2;
                Ys[(b0+1)*YP + i0 + 8] = v3;
            }
        } else {
            // U GEMM: rows (w-4)*32..+32, K=64, N=32
            float dU[2][4][4];
            #pragma unroll
            for (int mi = 0; mi < 2; mi++)
                #pragma unroll
                for (int ni = 0; ni < 4; ni++)
                    #pragma unroll
                    for (int q = 0; q < 4; q++) dU[mi][ni][q] = 0.f;
            const int rb = (w - 4)*32;
            #pragma unroll
            for (int kk = 0; kk < 8; kk++) {
                uint32_t a[2][4], bb[4][2];
                #pragma unroll
                for (int mi = 0; mi < 2; mi++) {
                    const float* ap = Hs + (rb + mi*16 + gr)*HP + kk*8 + tc;
                    a[mi][0] = __float_as_uint(ap[0]);
                    a[mi][1] = __float_as_uint(ap[8*HP]);
                    a[mi][2] = __float_as_uint(ap[4]);
                    a[mi][3] = __float_as_uint(ap[8*HP + 4]);
                }
                const float* bp = V + (kk*8 + tc)*VP + gr;
                #pragma unroll
                for (int ni = 0; ni < 4; ni++) {
                    bb[ni][0] = __float_as_uint(bp[ni*8]);
                    bb[ni][1] = __float_as_uint(bp[4*VP + ni*8]);
                }
                #pragma unroll
                for (int mi = 0; mi < 2; mi++)
                    #pragma unroll
                    for (int ni = 0; ni < 4; ni++)
                        mma8(dU[mi][ni], a[mi], bb[ni]);
            }
            // stash U into smem
            #pragma unroll
            for (int mi = 0; mi < 2; mi++) {
                int r0 = rb + mi*16 + gr;
                #pragma unroll
                for (int ni = 0; ni < 4; ni++) {
                    int cb = ni*8 + 2*tc;
                    *(float2*)&US[r0*UP + cb]     = make_float2(dU[mi][ni][0], dU[mi][ni][1]);
                    *(float2*)&US[(r0+8)*UP + cb] = make_float2(dU[mi][ni][2], dU[mi][ni][3]);
                }
            }
        }
        __syncthreads();   // V reads + US/Ys writes complete

        // coalesced Y write (all 256 threads): 2 float4 per thread
        {
            float4 a0 = *(const float4*)&Ys[yb*YP + yi];
            float4 a1 = *(const float4*)&Ys[yb*YP + yi + 4];
            size_t o = ((size_t)yb*HH + h)*LL + c*TT + yi;
            *(float4*)&ybase[o]     = a0;
            *(float4*)&ybase[o + 4] = a1;
        }

        // state update (fp32 regs), write tf32 copy into V; store next Z
        #pragma unroll
        for (int k = 0; k < 8; k++) {
            float ur = US[sn*UP + sb0 + k];
            float ui = US[(64 + sn)*UP + sb0 + k];
            float nr = fmaf(wtr, s_re[k], fmaf(-wti, s_im[k], ur));
            float ni_ = fmaf(wtr, s_im[k], fmaf(wti, s_re[k], ui));
            s_re[k] = nr; s_im[k] = ni_;
            V[(64 + sn)*VP + sb0 + k]  = rtf(nr);
            V[(128 + sn)*VP + sb0 + k] = rtf(ni_);
        }
        if (cc + 1 < NCH) {
            V[(jq*8+0)*VP + zb] = z0.x; V[(jq*8+1)*VP + zb] = z0.y;
            V[(jq*8+2)*VP + zb] = z0.z; V[(jq*8+3)*VP + zb] = z0.w;
            V[(jq*8+4)*VP + zb] = z1.x; V[(jq*8+5)*VP + zb] = z1.y;
            V[(jq*8+6)*VP + zb] = z1.z; V[(jq*8+7)*VP + zb] = z1.w;
        }
        __syncthreads();
    }

    // ---- ticket: second (h) finisher applies gelu(yf+yb) over all 32 b-rows ----
    __threadfence();
    __syncthreads();
    if (tid == 0) s_tkt = atomicAdd(&g_cnt[h], 1);
    __syncthreads();
    if (s_tkt == 1) {
        __threadfence();
        for (int q = tid; q < 32*(LL/4); q += 256) {
            int b = q >> 9, off = q & 511;
            size_t base4 = ((size_t)b*HH + h)*(LL/4) + off;
            float4 a = ((const float4*)g_yf)[base4];
            float4 bv = ((const float4*)g_yb)[base4];
            float4 o;
            o.x = rtf(geluf(a.x + bv.x));
            o.y = rtf(geluf(a.y + bv.y));
            o.z = rtf(geluf(a.z + bv.z));
            o.w = rtf(geluf(a.w + bv.w));
            ((float4*)g_yf)[base4] = o;
        }
    }
}

// ================= tf32 tensor-core GEMM stages (cp.async double-buffered) =================
#define PW 36
#define PB 72
#define WS_SZ (128*PW)
#define BS_SZ (32*PB)
#define S1_WORDS (WS_SZ + BS_SZ)
#define S2_WORDS (2*WS_SZ + BS_SZ)
#define S1_BYTES (2*S1_WORDS*4)
#define S2_BYTES (2*S2_WORDS*4)

__device__ __forceinline__ void cpw_issue(uint32_t wA, const float* __restrict__ W,
                                          int g0, int k0, int sk, int tid)
{
    int g = tid >> 1, h0 = (tid & 1) * 16;
    const float* src = W + (size_t)(g0 + g)*sk + k0 + h0;
    uint32_t dst = wA + (uint32_t)(g*PW + h0)*4u;
    #pragma unroll
    for (int i = 0; i < 4; i++) cpa16(dst + 16u*i, src + 4*i);
}
__device__ __forceinline__ void cpb_issue(uint32_t bA, const float* __restrict__ Act,
                                          int k0, int l0, int tid)
{
    int hh = tid >> 3, lo = (tid & 7) * 8;
    const float* src = Act + (size_t)(k0 + hh)*LL + l0 + lo;
    uint32_t dst = bA + (uint32_t)(hh*PB + lo)*4u;
    cpa16(dst, src);
    cpa16(dst + 16u, src + 4);
}

__device__ __forceinline__ void mma_chunk(float d[2][4][4], const uint32_t* Ws, const uint32_t* Bsm,
                                          int wg, int wl, int gr, int tc)
{
    #pragma unroll
    for (int ks = 0; ks < 4; ks++) {
        int kk = ks*8;
        uint32_t a[2][4], bb[4][2];
        #pragma unroll
        for (int mi = 0; mi < 2; mi++) {
            const uint32_t* p = Ws + (wg + mi*16 + gr)*PW + kk + tc;
            a[mi][0] = p[0];
            a[mi][1] = p[8*PW];
            a[mi][2] = p[4];
            a[mi][3] = p[8*PW + 4];
        }
        #pragma unroll
        for (int ni = 0; ni < 4; ni++) {
            const uint32_t* p = Bsm + (kk + tc)*PB + wl + ni*8 + gr;
            bb[ni][0] = p[0];
            bb[ni][1] = p[4*PB];
        }
        #pragma unroll
        for (int mi = 0; mi < 2; mi++)
            #pragma unroll
            for (int ni = 0; ni < 4; ni++)
                mma8(d[mi][ni], a[mi], bb[ni]);
    }
}

// ---------------- stage1 ----------------
__global__ __launch_bounds__(256) void k_stage1(const float* __restrict__ bout,
                         const float* __restrict__ x, const float* __restrict__ bf)
{
    extern __shared__ uint32_t dsm[];
    const int b  = blockIdx.z;
    const int g0 = blockIdx.y * 128;
    const int l0 = blockIdx.x * 64;
    const int tid = threadIdx.x;
    const int w = tid >> 5, lane = tid & 31;
    const int wg = (w >> 1) * 32, wl = (w & 1) * 32;
    const int gr = lane >> 2, tc = lane & 3;

    uint32_t sb = (uint32_t)__cvta_generic_to_shared(dsm);
    uint32_t wA[2] = { sb, sb + (uint32_t)S1_WORDS*4u };
    uint32_t bA[2] = { sb + (uint32_t)WS_SZ*4u, sb + (uint32_t)(S1_WORDS + WS_SZ)*4u };

    float d[2][4][4];
    #pragma unroll
    for (int mi = 0; mi < 2; mi++)
        #pragma unroll
        for (int ni = 0; ni < 4; ni++)
            #pragma unroll
            for (int q = 0; q < 4; q++) d[mi][ni][q] = 0.f;

    const float* act = g_yf + (size_t)b*HH*LL;
    const float* ft  = g_ft + (size_t)b*FF*LL;

    cpw_issue(wA[0], g_WoutT, g0, 0, HH, tid);
    cpb_issue(bA[0], act, 0, l0, tid);
    cp_commit();

    for (int c = 0; c < 9; c++) {
        int cb = c & 1;
        if (c + 1 < 9) {
            int nb = cb ^ 1;
            if (c + 1 < 8) {
                cpw_issue(wA[nb], g_WoutT, g0, (c+1)*32, HH, tid);
                cpb_issue(bA[nb], act, (c+1)*32, l0, tid);
            } else {
                cpw_issue(wA[nb], g_WfT, g0, 0, FF, tid);
                cpb_issue(bA[nb], ft, 0, l0, tid);
            }
            cp_commit();
            cp_wait1();
        } else {
            cp_wait0();
        }
        __syncthreads();
        mma_chunk(d, dsm + cb*S1_WORDS, dsm + cb*S1_WORDS + WS_SZ, wg, wl, gr, tc);
        __syncthreads();
    }

    #pragma unroll
    for (int mi = 0; mi < 2; mi++) {
        int ga = g0 + wg + mi*16 + gr;
        int gb2 = ga + 8;
        float basea = bout[ga]  + bf[ga]  + g_tb[b*HH + ga];
        float baseb = bout[gb2] + bf[gb2] + g_tb[b*HH + gb2];
        #pragma unroll
        for (int ni = 0; ni < 4; ni++) {
            int l = l0 + wl + ni*8 + 2*tc;
            size_t offa = ((size_t)b*HH + ga)*LL + l;
            size_t offb = ((size_t)b*HH + gb2)*LL + l;
            float2 xa = *(const float2*)(x + offa);
            float2 xb = *(const float2*)(x + offb);
            float2 ra, rb;
            ra.x = rtf(gatef(d[mi][ni][0] + basea + xa.x));
            ra.y = rtf(gatef(d[mi][ni][1] + basea + xa.y));
            rb.x = rtf(gatef(d[mi][ni][2] + baseb + xb.x));
            rb.y = rtf(gatef(d[mi][ni][3] + baseb + xb.y));
            *(float2*)(g_z + offa) = ra;
            *(float2*)(g_z + offb) = rb;
        }
    }
}

// ---------------- stage2 ----------------
__global__ __launch_bounds__(256) void k_stage2(const float* __restrict__ b1,
                         const float* __restrict__ b2,
                         const float* __restrict__ x, float* __restrict__ o1,
                         float* __restrict__ o2)
{
    extern __shared__ uint32_t dsm[];
    const int b  = blockIdx.z;
    const int g0 = blockIdx.y * 128;
    const int l0 = blockIdx.x * 64;
    const int tid = threadIdx.x;
    const int w = tid >> 5, lane = tid & 31;
    const int wg = (w >> 1) * 32, wl = (w & 1) * 32;
    const int gr = lane >> 2, tc = lane & 3;

    uint32_t sb = (uint32_t)__cvta_generic_to_shared(dsm);
    uint32_t w1A[2] = { sb, sb + (uint32_t)S2_WORDS*4u };
    uint32_t w2A[2] = { sb + (uint32_t)WS_SZ*4u, sb + (uint32_t)(S2_WORDS + WS_SZ)*4u };
    uint32_t bA[2]  = { sb + (uint32_t)(2*WS_SZ)*4u, sb + (uint32_t)(S2_WORDS + 2*WS_SZ)*4u };

    float d1[2][4][4], d2[2][4][4];
    #pragma unroll
    for (int mi = 0; mi < 2; mi++)
        #pragma unroll
        for (int ni = 0; ni < 4; ni++)
            #pragma unroll
            for (int q = 0; q < 4; q++) { d1[mi][ni][q] = 0.f; d2[mi][ni][q] = 0.f; }

    const float* gb = g_z + (size_t)b*HH*LL;

    cpw_issue(w1A[0], g_W1T, g0, 0, HH, tid);
    cpw_issue(w2A[0], g_W2T, g0, 0, HH, tid);
    cpb_issue(bA[0], gb, 0, l0, tid);
    cp_commit();

    for (int c = 0; c < 8; c++) {
        int cb = c & 1;
        if (c + 1 < 8) {
            int nb = cb ^ 1;
            cpw_issue(w1A[nb], g_W1T, g0, (c+1)*32, HH, tid);
            cpw_issue(w2A[nb], g_W2T, g0, (c+1)*32, HH, tid);
            cpb_issue(bA[nb], gb, (c+1)*32, l0, tid);
            cp_commit();
            cp_wait1();
        } else {
            cp_wait0();
        }
        __syncthreads();
        const uint32_t* W1s = dsm + cb*S2_WORDS;
        const uint32_t* W2s = W1s + WS_SZ;
        const uint32_t* Bsm = W1s + 2*WS_SZ;
        #pragma unroll
        for (int ks = 0; ks < 4; ks++) {
            int kk = ks*8;
            uint32_t a1[2][4], a2[2][4], bb[4][2];
            #pragma unroll
            for (int mi = 0; mi < 2; mi++) {
                const uint32_t* p1 = W1s + (wg + mi*16 + gr)*PW + kk + tc;
                a1[mi][0] = p1[0]; a1[mi][1] = p1[8*PW]; a1[mi][2] = p1[4]; a1[mi][3] = p1[8*PW + 4];
                const uint32_t* p2 = W2s + (wg + mi*16 + gr)*PW + kk + tc;
                a2[mi][0] = p2[0]; a2[mi][1] = p2[8*PW]; a2[mi][2] = p2[4]; a2[mi][3] = p2[8*PW + 4];
            }
            #pragma unroll
            for (int ni = 0; ni < 4; ni++) {
                const uint32_t* p = Bsm + (kk + tc)*PB + wl + ni*8 + gr;
                bb[ni][0] = p[0];
                bb[ni][1] = p[4*PB];
            }
            #pragma unroll
            for (int mi = 0; mi < 2; mi++)
                #pragma unroll
                for (int ni = 0; ni < 4; ni++) {
                    mma8(d1[mi][ni], a1[mi], bb[ni]);
                    mma8(d2[mi][ni], a2[mi], bb[ni]);
                }
        }
        __syncthreads();
    }

    #pragma unroll
    for (int mi = 0; mi < 2; mi++) {
        int ga = g0 + wg + mi*16 + gr;
        int gb2 = ga + 8;
        float b1a = b1[ga], b1b = b1[gb2];
        float b2a = b2[ga], b2b = b2[gb2];
        #pragma unroll
        for (int ni = 0; ni < 4; ni++) {
            int l = l0 + wl + ni*8 + 2*tc;
            size_t offa = ((size_t)b*HH + ga)*LL + l;
            size_t offb = ((size_t)b*HH + gb2)*LL + l;
            float2 xa = *(const float2*)(x + offa);
            float2 xb = *(const float2*)(x + offb);
            float2 r;
            r.x = d1[mi][ni][0] + b1a + xa.x;
            r.y = d1[mi][ni][1] + b1a + xa.y;
            *(float2*)(o1 + offa) = r;
            r.x = d1[mi][ni][2] + b1b + xb.x;
            r.y = d1[mi][ni][3] + b1b + xb.y;
            *(float2*)(o1 + offb) = r;
            r.x = d2[mi][ni][0] + b2a;
            r.y = d2[mi][ni][1] + b2a;
            *(float2*)(o2 + offa) = r;
            r.x = d2[mi][ni][2] + b2b;
            r.y = d2[mi][ni][3] + b2b;
            *(float2*)(o2 + offb) = r;
        }
    }
}

// ---------------- launch ----------------
extern "C" void kernel_launch(void* const* d_in, const int* in_sizes, int n_in,
                              void* d_out, int out_size)
{
    const float* x        = (const float*)d_in[0];
    const float* t        = (const float*)d_in[1];
    const float* feat     = (const float*)d_in[2];
    const float* Wt       = (const float*)d_in[3];
    const float* bt       = (const float*)d_in[4];
    const float* ln_g     = (const float*)d_in[5];
    const float* ln_b     = (const float*)d_in[6];
    const float* log_dt   = (const float*)d_in[7];
    const float* logA_real= (const float*)d_in[8];
    const float* A_imag   = (const float*)d_in[9];
    const float* C_re     = (const float*)d_in[10];
    const float* C_im     = (const float*)d_in[11];
    const float* Dv       = (const float*)d_in[12];
    const float* Wout     = (const float*)d_in[13];
    const float* bout     = (const float*)d_in[14];
    const float* W1       = (const float*)d_in[15];
    const float* b1       = (const float*)d_in[16];
    const float* W2       = (const float*)d_in[17];
    const float* b2       = (const float*)d_in[18];
    const float* Wf       = (const float*)d_in[19];
    const float* bf       = (const float*)d_in[20];

    float* o1 = (float*)d_out;
    float* o2 = (float*)d_out + (size_t)BHL;

    cudaFuncSetAttribute(k_cscan, cudaFuncAttributeMaxDynamicSharedMemorySize, CS_BYTES);
    cudaFuncSetAttribute(k_stage1, cudaFuncAttributeMaxDynamicSharedMemorySize, S1_BYTES);
    cudaFuncSetAttribute(k_stage2, cudaFuncAttributeMaxDynamicSharedMemorySize, S2_BYTES);

    k_cvtw<<<(HH*HH)/256, 256>>>(Wout, W1, W2, Wf);
    k_tb<<<dim3(4, BB), 256>>>(t, Wt, bt);
    k_prep<<<2*HH, 256>>>(log_dt, logA_real, A_imag, C_re, C_im);
    k_ln<<<dim3(LL/64, BB), 256>>>(x, ln_g, ln_b, feat);
    k_cscan<<<2*HH, 256, CS_BYTES>>>(Dv);
    k_stage1<<<dim3(LL/64, HH/128, BB), 256, S1_BYTES>>>(bout, x, bf);
    k_stage2<<<dim3(LL/64, HH/128, BB), 256, S2_BYTES>>>(b1, b2, x, o1, o2);
}

// round 16
// speedup vs baseline: 1.0924x; 1.0924x over previous
#include <cuda_runtime.h>
#include <math.h>
#include <stdint.h>

#define BB 32
#define HH 256
#define LL 2048
#define NS 64
#define FF 32
#define BHL (BB*HH*LL)
#define TT 64
#define NCH 32

// ---------------- tf32 helpers ----------------
__device__ __forceinline__ uint32_t tf32c(float x) {
    uint32_t r; asm("cvt.rna.tf32.f32 %0, %1;" : "=r"(r) : "f"(x)); return r;
}
__device__ __forceinline__ float rtf(float x) { return __uint_as_float(tf32c(x)); }
__device__ __forceinline__ void mma8(float d[4], const uint32_t a[4], const uint32_t b[2]) {
    asm("mma.sync.aligned.m16n8k8.row.col.f32.tf32.tf32.f32 "
        "{%0,%1,%2,%3}, {%4,%5,%6,%7}, {%8,%9}, {%0,%1,%2,%3};"
        : "+f"(d[0]), "+f"(d[1]), "+f"(d[2]), "+f"(d[3])
        : "r"(a[0]), "r"(a[1]), "r"(a[2]), "r"(a[3]), "r"(b[0]), "r"(b[1]));
}

// ---------------- cp.async helpers ----------------
__device__ __forceinline__ void cpa16(uint32_t s, const float* g) {
    asm volatile("cp.async.cg.shared.global [%0], [%1], 16;" :: "r"(s), "l"(g));
}
__device__ __forceinline__ void cp_commit() { asm volatile("cp.async.commit_group;"); }
__device__ __forceinline__ void cp_wait1()  { asm volatile("cp.async.wait_group 1;"); }
__device__ __forceinline__ void cp_wait0()  { asm volatile("cp.async.wait_group 0;"); }

__device__ __forceinline__ float gatef(float o) {
    float u = __expf(fminf(-o, 25.f));
    float u2 = u * u;
    return (1.f - u2) / ((1.f + u2) * (1.f + u));
}
__device__ __forceinline__ float geluf(float y) {
    float u = 0.7978845608028654f * fmaf(0.044715f*y, y*y, y);
    float e = __expf(fminf(-2.f*u, 80.f));
    float th = (1.f - e) / (1.f + e);
    return 0.5f*y*(1.f + th);
}

// ---------------- scratch ----------------
__device__ float g_tb[BB*HH];
__device__ float g_z [BHL];
__device__ float g_yf[BHL];   // fwd scan out; after ticket: tf32(gelu(yf+yb))
__device__ float g_yb[BHL];   // bwd scan out (+ D*z folded)
__device__ int   g_cnt[BB*HH];
// tf32-pre-rounded GEMM operands
__device__ float g_WoutT[HH*HH], g_W1T[HH*HH], g_W2T[HH*HH], g_WfT[HH*FF];
__device__ float g_ft[BB*FF*LL];
// chunked-scan matrices per (h,dir)
__device__ float g_G[2*HH][64*192];   // [Ktoeplitz | CO_re | -CO_im]
__device__ float g_H[2*HH][128*64];   // [WA_re ; WA_im]
__device__ float g_wTd[2*HH][128];    // w^64 re(0..63), im(64..127)

// ---------------- pre-round weights to tf32 (+ zero tickets) ----------------
__global__ void k_cvtw(const float* __restrict__ Wout, const float* __restrict__ W1,
                       const float* __restrict__ W2, const float* __restrict__ Wf)
{
    int i = blockIdx.x*256 + threadIdx.x;      // 0..65535
    g_WoutT[i] = rtf(Wout[i]);
    g_W1T[i]   = rtf(W1[i]);
    g_W2T[i]   = rtf(W2[i]);
    if (i < HH*FF) g_WfT[i] = rtf(Wf[i]);
    if (i < HH) g_cnt[i] = 0;
}

// ---------------- t @ Wt^T + bt ----------------
__global__ void k_tb(const float* __restrict__ t, const float* __restrict__ Wt,
                     const float* __restrict__ bt)
{
    __shared__ float ts[HH];
    __shared__ float part[64][4];
    int b  = blockIdx.y;
    int h0 = blockIdx.x * 64;
    int tid = threadIdx.x;
    ts[tid] = t[b*HH + tid];
    __syncthreads();
    int hl = tid >> 2, ks = tid & 3;
    int h = h0 + hl;
    const float* wrow = Wt + (size_t)h*HH + ks*64;
    const float* tsp  = ts + ks*64;
    float acc = 0.f;
    #pragma unroll 16
    for (int k = 0; k < 64; k++) acc = fmaf(tsp[k], wrow[k], acc);
    part[hl][ks] = acc;
    __syncthreads();
    if (ks == 0)
        g_tb[b*HH + h] = part[hl][0] + part[hl][1] + part[hl][2] + part[hl][3] + bt[h];
}

// ---------------- chunked-scan matrix prep: one block per (h,dir) ----------------
__global__ void k_prep(const float* __restrict__ log_dt, const float* __restrict__ logA_real,
                       const float* __restrict__ A_imag, const float* __restrict__ C_re,
                       const float* __restrict__ C_im)
{
    __shared__ float Ere[65][64], Eim[65][64];
    __shared__ float cdr[64], cdi[64], kv[64], sdr[64], sdi[64];
    int hd = blockIdx.x, h = hd >> 1, dir = hd & 1;
    int tid = threadIdx.x;
    if (tid < 64) {
        int n = tid, i = h*NS + n;
        float dt = expf(log_dt[h]);
        float Ar = -expf(logA_real[i]);
        float Ai = A_imag[i];
        float dr = dt*Ar, di = dt*Ai;
        sdr[n] = dr; sdi[n] = di;
        float er = expf(dr);
        float wr = er*cosf(di), wi = er*sinf(di);
        float Er = wr - 1.f, Ei = wi;
        float inv = 1.f/(Ar*Ar + Ai*Ai);
        float qr = (Er*Ar + Ei*Ai)*inv;
        float qi = (Ei*Ar - Er*Ai)*inv;
        float cr = C_re[dir*HH*NS + i], ci = C_im[dir*HH*NS + i];
        cdr[n] = 2.f*(cr*qr - ci*qi);
        cdi[n] = 2.f*(cr*qi + ci*qr);
    }
    __syncthreads();
    for (int q = tid; q < 65*64; q += 256) {
        int p = q >> 6, n = q & 63;
        float e  = expf((float)p*sdr[n]);
        float ph = (float)p*sdi[n];
        Ere[p][n] = e*cosf(ph);
        Eim[p][n] = e*sinf(ph);
    }
    __syncthreads();
    if (tid < 64) {
        int p = tid;
        float acc = 0.f;
        for (int n = 0; n < 64; n++) acc += cdr[n]*Ere[p][n] - cdi[n]*Eim[p][n];
        kv[p] = acc;
    }
    __syncthreads();
    float* Gp = g_G[hd];
    for (int q = tid; q < 64*192; q += 256) {
        int i = q / 192, col = q % 192;
        float val;
        if (col < 64) {
            int j = col;
            if (!dir) val = (j <= i) ? kv[i-j] : 0.f;
            else      val = (j >  i) ? kv[j-i-1] : 0.f;   // z[l+1] carries w^0
        } else {
            int n = (col - 64) & 63;
            int p = dir ? (63 - i) : (i + 1);
            float core = cdr[n]*Ere[p][n] - cdi[n]*Eim[p][n];
            float coim = cdr[n]*Eim[p][n] + cdi[n]*Ere[p][n];
            val = (col < 128) ? core : -coim;
        }
        Gp[q] = rtf(val);
    }
    float* Hp = g_H[hd];
    for (int q = tid; q < 128*64; q += 256) {
        int r = q >> 6, j = q & 63;
        int n = r & 63;
        int p = dir ? j : (63 - j);                        // S gathers w^j
        float val = (r < 64) ? Ere[p][n] : Eim[p][n];
        Hp[q] = rtf(val);
    }
    if (tid < 64) {
        g_wTd[hd][tid]    = Ere[64][tid];
        g_wTd[hd][64+tid] = Eim[64][tid];
    }
}

// ---------------- LayerNorm over H -> z (tf32-rounded) + feat tf32 tail ----------------
__global__ void k_ln(const float* __restrict__ x, const float* __restrict__ ln_g,
                     const float* __restrict__ ln_b, const float* __restrict__ feat)
{
    __shared__ float tbs[HH], gs[HH], bs[HH];
    __shared__ float sms[4][64], smss[4][64];
    int b = blockIdx.y;
    int tid = threadIdx.x;
    tbs[tid] = g_tb[b*HH + tid];
    gs[tid]  = ln_g[tid];
    bs[tid]  = ln_b[tid];
    __syncthreads();
    int lg = tid & 63, hg = tid >> 6;
    int l = blockIdx.x*64 + lg;
    const float* xb = x + (size_t)b*HH*LL + l;
    float s = 0.f, ss = 0.f;
    #pragma unroll 8
    for (int h = hg*64; h < hg*64 + 64; h++) {
        float v = xb[(size_t)h*LL] + tbs[h];
        s += v; ss = fmaf(v, v, ss);
    }
    sms[hg][lg] = s; smss[hg][lg] = ss;
    __syncthreads();
    float st  = sms[0][lg]  + sms[1][lg]  + sms[2][lg]  + sms[3][lg];
    float sst = smss[0][lg] + smss[1][lg] + smss[2][lg] + smss[3][lg];
    float mu  = st * (1.0f/HH);
    float var = sst*(1.0f/HH) - mu*mu;
    float rstd = rsqrtf(var + 1e-5f);
    float* zb = g_z + (size_t)b*HH*LL + l;
    #pragma unroll 8
    for (int h = hg*64; h < hg*64 + 64; h++) {
        float v = xb[(size_t)h*LL] + tbs[h];
        zb[(size_t)h*LL] = rtf((v - mu)*rstd*gs[h] + bs[h]);
    }
    // tail: feat -> tf32 pre-round
    {
        int gidx = (b*32 + blockIdx.x)*256 + tid;
        const float4* fs = (const float4*)feat;
        float4* fd = (float4*)g_ft;
        #pragma unroll
        for (int q = 0; q < 2; q++) {
            float4 v = fs[gidx*2 + q];
            v.x = rtf(v.x); v.y = rtf(v.y); v.z = rtf(v.z); v.w = rtf(v.w);
            fd[gidx*2 + q] = v;
        }
    }
}

// ---------------- chunked scan: one CTA per (h,dir), 512 threads / 16 warps ----------------
#define GP 196
#define HP 68
#define VP 40
#define UP 40
#define CS_WORDS (64*GP + 128*HP + 192*VP + 128*UP)
#define CS_BYTES (CS_WORDS*4)

__global__ __launch_bounds__(512) void k_cscan(const float* __restrict__ Dv)
{
    extern __shared__ float sm[];
    float* Gs = sm;                 // 64 x GP
    float* Hs = Gs + 64*GP;         // 128 x HP
    float* V  = Hs + 128*HP;        // 192 x VP : [Z(64); S_re(64); S_im(64)] x 32b
    float* US = V  + 192*VP;        // 128 x UP
    __shared__ int s_tkt;

    const int hd = blockIdx.x, h = hd >> 1, dir = hd & 1;
    const int tid = threadIdx.x;
    const int w = tid >> 5, lane = tid & 31;
    const int gr = lane >> 2, tc = lane & 3;

    // load G, H into smem
    {
        const float4* gsrc = (const float4*)g_G[hd];
        for (int q = tid; q < 64*48; q += 512) {
            int row = q / 48, c4 = q % 48;
            *(float4*)&Gs[row*GP + c4*4] = gsrc[q];
        }
        const float4* hsrc = (const float4*)g_H[hd];
        for (int q = tid; q < 128*16; q += 512) {
            int row = q / 16, c4 = q % 16;
            *(float4*)&Hs[row*HP + c4*4] = hsrc[q];
        }
    }
    // zero state region of V
    for (int q = tid; q < 128*32; q += 512)
        V[(64 + (q >> 5))*VP + (q & 31)] = 0.f;

    // fp32 state registers: thread owns mode sn = tid>>3, batch sb0 = (tid&7)*4 .. +3
    const int sn = tid >> 3, sb0 = (tid & 7)*4;
    float s_re[4], s_im[4];
    #pragma unroll
    for (int k = 0; k < 4; k++) { s_re[k] = 0.f; s_im[k] = 0.f; }
    const float wtr = g_wTd[hd][sn], wti = g_wTd[hd][64 + sn];
    const float dD = dir ? Dv[h] : 0.f;

    // z chunk loading: thread (zb, jq) loads one float4 at j = jq*4
    const int zb = tid >> 4, jq = tid & 15;
    const float* zbase = g_z + ((size_t)zb*HH + h)*LL;
    float* ybase = dir ? g_yb : g_yf;

    const int ch0 = dir ? (NCH - 1) : 0;
    const int stp = dir ? -1 : 1;
    {
        float4 z0 = *(const float4*)&zbase[ch0*TT + jq*4];
        V[(jq*4+0)*VP + zb] = z0.x; V[(jq*4+1)*VP + zb] = z0.y;
        V[(jq*4+2)*VP + zb] = z0.z; V[(jq*4+3)*VP + zb] = z0.w;
    }
    __syncthreads();

    for (int cc = 0; cc < NCH; cc++) {
        int c = ch0 + stp*cc;
        // prefetch next chunk's z (one coalesced float4)
        float4 z0;
        if (cc + 1 < NCH) {
            int cn = c + stp;
            z0 = *(const float4*)&zbase[cn*TT + jq*4];
        }

        if (w < 8) {
            // Y GEMM: m-tile (w>>1)*16, n-half (w&1)*16; K=192
            const int tm = w >> 1, nh = w & 1;
            float dY[2][4];
            #pragma unroll
            for (int ni = 0; ni < 2; ni++)
                #pragma unroll
                for (int q = 0; q < 4; q++) dY[ni][q] = 0.f;
            const float* Ab = Gs + (tm*16 + gr)*GP + tc;
            #pragma unroll
            for (int kk = 0; kk < 24; kk++) {
                uint32_t a[4], bb[2][2];
                const float* ap = Ab + kk*8;
                a[0] = __float_as_uint(ap[0]);
                a[1] = __float_as_uint(ap[8*GP]);
                a[2] = __float_as_uint(ap[4]);
                a[3] = __float_as_uint(ap[8*GP + 4]);
                const float* bp = V + (kk*8 + tc)*VP + nh*16 + gr;
                #pragma unroll
                for (int ni = 0; ni < 2; ni++) {
                    bb[ni][0] = __float_as_uint(bp[ni*8]);
                    bb[ni][1] = __float_as_uint(bp[4*VP + ni*8]);
                }
                #pragma unroll
                for (int ni = 0; ni < 2; ni++) mma8(dY[ni], a, bb[ni]);
            }
            // write Y (+ D*z for bwd)
            int i0 = tm*16 + gr;
            #pragma unroll
            for (int ni = 0; ni < 2; ni++) {
                int b0 = nh*16 + ni*8 + 2*tc;
                float v0 = dY[ni][0], v1 = dY[ni][1], v2 = dY[ni][2], v3 = dY[ni][3];
                if (dir) {
                    v0 = fmaf(dD, V[i0*VP + b0],       v0);
                    v1 = fmaf(dD, V[i0*VP + b0 + 1],   v1);
                    v2 = fmaf(dD, V[(i0+8)*VP + b0],   v2);
                    v3 = fmaf(dD, V[(i0+8)*VP + b0+1], v3);
                }
                size_t o0 = ((size_t)b0*HH + h)*LL + c*TT + i0;
                size_t o1 = ((size_t)(b0+1)*HH + h)*LL + c*TT + i0;
                ybase[o0]     = v0;
                ybase[o1]     = v1;
                ybase[o0 + 8] = v2;
                ybase[o1 + 8] = v3;
            }
        } else {
            // U GEMM: warp u = w-8: rows (u>>1)*32 (2 m16 tiles), n-half (u&1)*16; K=64
            const int u = w - 8;
            const int rb = (u >> 1)*32, nh = u & 1;
            float dU[2][2][4];
            #pragma unroll
            for (int mi = 0; mi < 2; mi++)
                #pragma unroll
                for (int ni = 0; ni < 2; ni++)
                    #pragma unroll
                    for (int q = 0; q < 4; q++) dU[mi][ni][q] = 0.f;
            #pragma unroll
            for (int kk = 0; kk < 8; kk++) {
                uint32_t a[2][4], bb[2][2];
                #pragma unroll
                for (int mi = 0; mi < 2; mi++) {
                    const float* ap = Hs + (rb + mi*16 + gr)*HP + kk*8 + tc;
                    a[mi][0] = __float_as_uint(ap[0]);
                    a[mi][1] = __float_as_uint(ap[8*HP]);
                    a[mi][2] = __float_as_uint(ap[4]);
                    a[mi][3] = __float_as_uint(ap[8*HP + 4]);
                }
                const float* bp = V + (kk*8 + tc)*VP + nh*16 + gr;
                #pragma unroll
                for (int ni = 0; ni < 2; ni++) {
                    bb[ni][0] = __float_as_uint(bp[ni*8]);
                    bb[ni][1] = __float_as_uint(bp[4*VP + ni*8]);
                }
                #pragma unroll
                for (int mi = 0; mi < 2; mi++)
                    #pragma unroll
                    for (int ni = 0; ni < 2; ni++)
                        mma8(dU[mi][ni], a[mi], bb[ni]);
            }
            // stash U into smem
            #pragma unroll
            for (int mi = 0; mi < 2; mi++) {
                int r0 = rb + mi*16 + gr;
                #pragma unroll
                for (int ni = 0; ni < 2; ni++) {
                    int cb = nh*16 + ni*8 + 2*tc;
                    *(float2*)&US[r0*UP + cb]     = make_float2(dU[mi][ni][0], dU[mi][ni][1]);
                    *(float2*)&US[(r0+8)*UP + cb] = make_float2(dU[mi][ni][2], dU[mi][ni][3]);
                }
            }
        }
        __syncthreads();   // V reads + US writes complete

        // state update (fp32 regs), write tf32 copy into V; store next Z
        #pragma unroll
        for (int k = 0; k < 4; k++) {
            float ur = US[sn*UP + sb0 + k];
            float ui = US[(64 + sn)*UP + sb0 + k];
            float nr = fmaf(wtr, s_re[k], fmaf(-wti, s_im[k], ur));
            float ni_ = fmaf(wtr, s_im[k], fmaf(wti, s_re[k], ui));
            s_re[k] = nr; s_im[k] = ni_;
            V[(64 + sn)*VP + sb0 + k]  = rtf(nr);
            V[(128 + sn)*VP + sb0 + k] = rtf(ni_);
        }
        if (cc + 1 < NCH) {
            V[(jq*4+0)*VP + zb] = z0.x; V[(jq*4+1)*VP + zb] = z0.y;
            V[(jq*4+2)*VP + zb] = z0.z; V[(jq*4+3)*VP + zb] = z0.w;
        }
        __syncthreads();
    }

    // ---- ticket: second (h) finisher applies gelu(yf+yb) over all 32 b-rows ----
    __threadfence();
    __syncthreads();
    if (tid == 0) s_tkt = atomicAdd(&g_cnt[h], 1);
    __syncthreads();
    if (s_tkt == 1) {
        __threadfence();
        for (int q = tid; q < 32*(LL/4); q += 512) {
            int b = q >> 9, off = q & 511;
            size_t base4 = ((size_t)b*HH + h)*(LL/4) + off;
            float4 a = ((const float4*)g_yf)[base4];
            float4 bv = ((const float4*)g_yb)[base4];
            float4 o;
            o.x = rtf(geluf(a.x + bv.x));
            o.y = rtf(geluf(a.y + bv.y));
            o.z = rtf(geluf(a.z + bv.z));
            o.w = rtf(geluf(a.w + bv.w));
            ((float4*)g_yf)[base4] = o;
        }
    }
}

// ================= tf32 tensor-core GEMM stages (cp.async double-buffered) =================
#define PW 36
#define PB 72
#define WS_SZ (128*PW)
#define BS_SZ (32*PB)
#define S1_WORDS (WS_SZ + BS_SZ)
#define S2_WORDS (2*WS_SZ + BS_SZ)
#define S1_BYTES (2*S1_WORDS*4)
#define S2_BYTES (2*S2_WORDS*4)

__device__ __forceinline__ void cpw_issue(uint32_t wA, const float* __restrict__ W,
                                          int g0, int k0, int sk, int tid)
{
    int g = tid >> 1, h0 = (tid & 1) * 16;
    const float* src = W + (size_t)(g0 + g)*sk + k0 + h0;
    uint32_t dst = wA + (uint32_t)(g*PW + h0)*4u;
    #pragma unroll
    for (int i = 0; i < 4; i++) cpa16(dst + 16u*i, src + 4*i);
}
__device__ __forceinline__ void cpb_issue(uint32_t bA, const float* __restrict__ Act,
                                          int k0, int l0, int tid)
{
    int hh = tid >> 3, lo = (tid & 7) * 8;
    const float* src = Act + (size_t)(k0 + hh)*LL + l0 + lo;
    uint32_t dst = bA + (uint32_t)(hh*PB + lo)*4u;
    cpa16(dst, src);
    cpa16(dst + 16u, src + 4);
}

__device__ __forceinline__ void mma_chunk(float d[2][4][4], const uint32_t* Ws, const uint32_t* Bsm,
                                          int wg, int wl, int gr, int tc)
{
    #pragma unroll
    for (int ks = 0; ks < 4; ks++) {
        int kk = ks*8;
        uint32_t a[2][4], bb[4][2];
        #pragma unroll
        for (int mi = 0; mi < 2; mi++) {
            const uint32_t* p = Ws + (wg + mi*16 + gr)*PW + kk + tc;
            a[mi][0] = p[0];
            a[mi][1] = p[8*PW];
            a[mi][2] = p[4];
            a[mi][3] = p[8*PW + 4];
        }
        #pragma unroll
        for (int ni = 0; ni < 4; ni++) {
            const uint32_t* p = Bsm + (kk + tc)*PB + wl + ni*8 + gr;
            bb[ni][0] = p[0];
            bb[ni][1] = p[4*PB];
        }
        #pragma unroll
        for (int mi = 0; mi < 2; mi++)
            #pragma unroll
            for (int ni = 0; ni < 4; ni++)
                mma8(d[mi][ni], a[mi], bb[ni]);
    }
}

// ---------------- stage1 ----------------
__global__ __launch_bounds__(256) void k_stage1(const float* __restrict__ bout,
                         const float* __restrict__ x, const float* __restrict__ bf)
{
    extern __shared__ uint32_t dsm[];
    const int b  = blockIdx.z;
    const int g0 = blockIdx.y * 128;
    const int l0 = blockIdx.x * 64;
    const int tid = threadIdx.x;
    const int w = tid >> 5, lane = tid & 31;
    const int wg = (w >> 1) * 32, wl = (w & 1) * 32;
    const int gr = lane >> 2, tc = lane & 3;

    uint32_t sb = (uint32_t)__cvta_generic_to_shared(dsm);
    uint32_t wA[2] = { sb, sb + (uint32_t)S1_WORDS*4u };
    uint32_t bA[2] = { sb + (uint32_t)WS_SZ*4u, sb + (uint32_t)(S1_WORDS + WS_SZ)*4u };

    float d[2][4][4];
    #pragma unroll
    for (int mi = 0; mi < 2; mi++)
        #pragma unroll
        for (int ni = 0; ni < 4; ni++)
            #pragma unroll
            for (int q = 0; q < 4; q++) d[mi][ni][q] = 0.f;

    const float* act = g_yf + (size_t)b*HH*LL;
    const float* ft  = g_ft + (size_t)b*FF*LL;

    cpw_issue(wA[0], g_WoutT, g0, 0, HH, tid);
    cpb_issue(bA[0], act, 0, l0, tid);
    cp_commit();

    for (int c = 0; c < 9; c++) {
        int cb = c & 1;
        if (c + 1 < 9) {
            int nb = cb ^ 1;
            if (c + 1 < 8) {
                cpw_issue(wA[nb], g_WoutT, g0, (c+1)*32, HH, tid);
                cpb_issue(bA[nb], act, (c+1)*32, l0, tid);
            } else {
                cpw_issue(wA[nb], g_WfT, g0, 0, FF, tid);
                cpb_issue(bA[nb], ft, 0, l0, tid);
            }
            cp_commit();
            cp_wait1();
        } else {
            cp_wait0();
        }
        __syncthreads();
        mma_chunk(d, dsm + cb*S1_WORDS, dsm + cb*S1_WORDS + WS_SZ, wg, wl, gr, tc);
        __syncthreads();
    }

    #pragma unroll
    for (int mi = 0; mi < 2; mi++) {
        int ga = g0 + wg + mi*16 + gr;
        int gb2 = ga + 8;
        float basea = bout[ga]  + bf[ga]  + g_tb[b*HH + ga];
        float baseb = bout[gb2] + bf[gb2] + g_tb[b*HH + gb2];
        #pragma unroll
        for (int ni = 0; ni < 4; ni++) {
            int l = l0 + wl + ni*8 + 2*tc;
            size_t offa = ((size_t)b*HH + ga)*LL + l;
            size_t offb = ((size_t)b*HH + gb2)*LL + l;
            float2 xa = *(const float2*)(x + offa);
            float2 xb = *(const float2*)(x + offb);
            float2 ra, rb;
            ra.x = rtf(gatef(d[mi][ni][0] + basea + xa.x));
            ra.y = rtf(gatef(d[mi][ni][1] + basea + xa.y));
            rb.x = rtf(gatef(d[mi][ni][2] + baseb + xb.x));
            rb.y = rtf(gatef(d[mi][ni][3] + baseb + xb.y));
            *(float2*)(g_z + offa) = ra;
            *(float2*)(g_z + offb) = rb;
        }
    }
}

// ---------------- stage2 ----------------
__global__ __launch_bounds__(256) void k_stage2(const float* __restrict__ b1,
                         const float* __restrict__ b2,
                         const float* __restrict__ x, float* __restrict__ o1,
                         float* __restrict__ o2)
{
    extern __shared__ uint32_t dsm[];
    const int b  = blockIdx.z;
    const int g0 = blockIdx.y * 128;
    const int l0 = blockIdx.x * 64;
    const int tid = threadIdx.x;
    const int w = tid >> 5, lane = tid & 31;
    const int wg = (w >> 1) * 32, wl = (w & 1) * 32;
    const int gr = lane >> 2, tc = lane & 3;

    uint32_t sb = (uint32_t)__cvta_generic_to_shared(dsm);
    uint32_t w1A[2] = { sb, sb + (uint32_t)S2_WORDS*4u };
    uint32_t w2A[2] = { sb + (uint32_t)WS_SZ*4u, sb + (uint32_t)(S2_WORDS + WS_SZ)*4u };
    uint32_t bA[2]  = { sb + (uint32_t)(2*WS_SZ)*4u, sb + (uint32_t)(S2_WORDS + 2*WS_SZ)*4u };

    float d1[2][4][4], d2[2][4][4];
    #pragma unroll
    for (int mi = 0; mi < 2; mi++)
        #pragma unroll
        for (int ni = 0; ni < 4; ni++)
            #pragma unroll
            for (int q = 0; q < 4; q++) { d1[mi][ni][q] = 0.f; d2[mi][ni][q] = 0.f; }

    const float* gb = g_z + (size_t)b*HH*LL;

    cpw_issue(w1A[0], g_W1T, g0, 0, HH, tid);
    cpw_issue(w2A[0], g_W2T, g0, 0, HH, tid);
    cpb_issue(bA[0], gb, 0, l0, tid);
    cp_commit();

    for (int c = 0; c < 8; c++) {
        int cb = c & 1;
        if (c + 1 < 8) {
            int nb = cb ^ 1;
            cpw_issue(w1A[nb], g_W1T, g0, (c+1)*32, HH, tid);
            cpw_issue(w2A[nb], g_W2T, g0, (c+1)*32, HH, tid);
            cpb_issue(bA[nb], gb, (c+1)*32, l0, tid);
            cp_commit();
            cp_wait1();
        } else {
            cp_wait0();
        }
        __syncthreads();
        const uint32_t* W1s = dsm + cb*S2_WORDS;
        const uint32_t* W2s = W1s + WS_SZ;
        const uint32_t* Bsm = W1s + 2*WS_SZ;
        #pragma unroll
        for (int ks = 0; ks < 4; ks++) {
            int kk = ks*8;
            uint32_t a1[2][4], a2[2][4], bb[4][2];
            #pragma unroll
            for (int mi = 0; mi < 2; mi++) {
                const uint32_t* p1 = W1s + (wg + mi*16 + gr)*PW + kk + tc;
                a1[mi][0] = p1[0]; a1[mi][1] = p1[8*PW]; a1[mi][2] = p1[4]; a1[mi][3] = p1[8*PW + 4];
                const uint32_t* p2 = W2s + (wg + mi*16 + gr)*PW + kk + tc;
                a2[mi][0] = p2[0]; a2[mi][1] = p2[8*PW]; a2[mi][2] = p2[4]; a2[mi][3] = p2[8*PW + 4];
            }
            #pragma unroll
            for (int ni = 0; ni < 4; ni++) {
                const uint32_t* p = Bsm + (kk + tc)*PB + wl + ni*8 + gr;
                bb[ni][0] = p[0];
                bb[ni][1] = p[4*PB];
            }
            #pragma unroll
            for (int mi = 0; mi < 2; mi++)
                #pragma unroll
                for (int ni = 0; ni < 4; ni++) {
                    mma8(d1[mi][ni], a1[mi], bb[ni]);
                    mma8(d2[mi][ni], a2[mi], bb[ni]);
                }
        }
        __syncthreads();
    }

    #pragma unroll
    for (int mi = 0; mi < 2; mi++) {
        int ga = g0 + wg + mi*16 + gr;
        int gb2 = ga + 8;
        float b1a = b1[ga], b1b = b1[gb2];
        float b2a = b2[ga], b2b = b2[gb2];
        #pragma unroll
        for (int ni = 0; ni < 4; ni++) {
            int l = l0 + wl + ni*8 + 2*tc;
            size_t offa = ((size_t)b*HH + ga)*LL + l;
            size_t offb = ((size_t)b*HH + gb2)*LL + l;
            float2 xa = *(const float2*)(x + offa);
            float2 xb = *(const float2*)(x + offb);
            float2 r;
            r.x = d1[mi][ni][0] + b1a + xa.x;
            r.y = d1[mi][ni][1] + b1a + xa.y;
            *(float2*)(o1 + offa) = r;
            r.x = d1[mi][ni][2] + b1b + xb.x;
            r.y = d1[mi][ni][3] + b1b + xb.y;
            *(float2*)(o1 + offb) = r;
            r.x = d2[mi][ni][0] + b2a;
            r.y = d2[mi][ni][1] + b2a;
            *(float2*)(o2 + offa) = r;
            r.x = d2[mi][ni][2] + b2b;
            r.y = d2[mi][ni][3] + b2b;
            *(float2*)(o2 + offb) = r;
        }
    }
}

// ---------------- launch ----------------
extern "C" void kernel_launch(void* const* d_in, const int* in_sizes, int n_in,
                              void* d_out, int out_size)
{
    const float* x        = (const float*)d_in[0];
    const float* t        = (const float*)d_in[1];
    const float* feat     = (const float*)d_in[2];
    const float* Wt       = (const float*)d_in[3];
    const float* bt       = (const float*)d_in[4];
    const float* ln_g     = (const float*)d_in[5];
    const float* ln_b     = (const float*)d_in[6];
    const float* log_dt   = (const float*)d_in[7];
    const float* logA_real= (const float*)d_in[8];
    const float* A_imag   = (const float*)d_in[9];
    const float* C_re     = (const float*)d_in[10];
    const float* C_im     = (const float*)d_in[11];
    const float* Dv       = (const float*)d_in[12];
    const float* Wout     = (const float*)d_in[13];
    const float* bout     = (const float*)d_in[14];
    const float* W1       = (const float*)d_in[15];
    const float* b1       = (const float*)d_in[16];
    const float* W2       = (const float*)d_in[17];
    const float* b2       = (const float*)d_in[18];
    const float* Wf       = (const float*)d_in[19];
    const float* bf       = (const float*)d_in[20];

    float* o1 = (float*)d_out;
    float* o2 = (float*)d_out + (size_t)BHL;

    cudaFuncSetAttribute(k_cscan, cudaFuncAttributeMaxDynamicSharedMemorySize, CS_BYTES);
    cudaFuncSetAttribute(k_stage1, cudaFuncAttributeMaxDynamicSharedMemorySize, S1_BYTES);
    cudaFuncSetAttribute(k_stage2, cudaFuncAttributeMaxDynamicSharedMemorySize, S2_BYTES);

    k_cvtw<<<(HH*HH)/256, 256>>>(Wout, W1, W2, Wf);
    k_tb<<<dim3(4, BB), 256>>>(t, Wt, bt);
    k_prep<<<2*HH, 256>>>(log_dt, logA_real, A_imag, C_re, C_im);
    k_ln<<<dim3(LL/64, BB), 256>>>(x, ln_g, ln_b, feat);
    k_cscan<<<2*HH, 512, CS_BYTES>>>(Dv);
    k_stage1<<<dim3(LL/64, HH/128, BB), 256, S1_BYTES>>>(bout, x, bf);
    k_stage2<<<dim3(LL/64, HH/128, BB), 256, S2_BYTES>>>(b1, b2, x, o1, o2);
}